// round 8
// baseline (speedup 1.0000x reference)
#include <cuda_runtime.h>
#include <math.h>

// ---------------- problem constants ----------------
#define NTREES   32
#define NPG      4095
#define NTOT     (NTREES * NPG)      // 131040
#define EDIM     256
#define HDIM     256
#define IOUD     768
#define CDIM     104
#define VOCABSZ  20000
#define PADTOK   (VOCABSZ - 1)       // 19999

// ---------------- scratch (device globals; no allocations allowed) ----------------
__device__ float g_tab  [(size_t)VOCABSZ * IOUD];         // emb @ W_iou^T + b_iou  (61.4 MB)
__device__ float g_h    [(size_t)NTOT * HDIM];            // hidden states
__device__ float g_c    [(size_t)NTOT * HDIM];            // cell states
__device__ float g_htild[(size_t)NTREES * 1024 * HDIM];   // segment sum of child h
__device__ float g_cagg [(size_t)NTREES * 1024 * HDIM];   // segment sum of f * child c
__device__ float g_uadd [(size_t)NTREES * 1024 * IOUD];   // htild @ U_iou^T per level

__device__ __forceinline__ float sigf(float v) { return 1.f / (1.f + __expf(-v)); }

// ============================================================================
// Kernel 1: vocab table GEMM.  g_tab[v][j] = dot(emb[v], W_iou[j]) + b_iou[j]
// (emb row for PAD token treated as zero, per reference emb.at[PAD].set(0))
// Tile: 64x64, BK=16, 256 threads, 4x4 micro-tile.
// ============================================================================
__global__ __launch_bounds__(256) void tab_kernel(
    const float* __restrict__ emb,    // [VOCAB, 256]
    const float* __restrict__ W,      // [768, 256]
    const float* __restrict__ bias)   // [768]
{
    __shared__ float As[16][68];
    __shared__ float Bs[16][68];
    int m0 = blockIdx.x * 64, n0 = blockIdx.y * 64;
    int tid = threadIdx.x;
    int tx = tid & 15, ty = tid >> 4;
    int lm = tid >> 2, lk = (tid & 3) * 4;

    float acc[4][4] = {};
    int arow_idx = m0 + lm;
    bool aval = (arow_idx < VOCABSZ) && (arow_idx != PADTOK);
    const float* arow = emb + (size_t)arow_idx * EDIM + lk;
    const float* brow = W + (size_t)(n0 + lm) * EDIM + lk;

    for (int k0 = 0; k0 < EDIM; k0 += 16) {
        float4 av = aval ? *(const float4*)(arow + k0) : make_float4(0.f, 0.f, 0.f, 0.f);
        As[lk + 0][lm] = av.x; As[lk + 1][lm] = av.y; As[lk + 2][lm] = av.z; As[lk + 3][lm] = av.w;
        float4 bv = *(const float4*)(brow + k0);
        Bs[lk + 0][lm] = bv.x; Bs[lk + 1][lm] = bv.y; Bs[lk + 2][lm] = bv.z; Bs[lk + 3][lm] = bv.w;
        __syncthreads();
#pragma unroll
        for (int kk = 0; kk < 16; ++kk) {
            float4 a4 = *(const float4*)&As[kk][ty * 4];
            float4 b4 = *(const float4*)&Bs[kk][tx * 4];
            float ar[4] = {a4.x, a4.y, a4.z, a4.w};
            float br[4] = {b4.x, b4.y, b4.z, b4.w};
#pragma unroll
            for (int i = 0; i < 4; ++i)
#pragma unroll
                for (int j = 0; j < 4; ++j) acc[i][j] += ar[i] * br[j];
        }
        __syncthreads();
    }
    float bb[4];
#pragma unroll
    for (int j = 0; j < 4; ++j) bb[j] = bias[n0 + tx * 4 + j];
#pragma unroll
    for (int i = 0; i < 4; ++i) {
        int r = m0 + ty * 4 + i;
        if (r < VOCABSZ) {
            float* o = g_tab + (size_t)r * IOUD + n0 + tx * 4;
#pragma unroll
            for (int j = 0; j < 4; ++j) o[j] = acc[i][j] + bb[j];
        }
    }
}

// ============================================================================
// Kernel 2: forget gate GEMM + segment scatter for children of one level.
// Rows = children at level d+1 (M = B * 2^(d+1)).
// f = sigmoid(h_child @ U_f_w^T + U_f_b); atomicAdd htild[slot] += h_child,
// cagg[slot] += f * c_child, where slot is the parent's slot at level d.
// ============================================================================
__global__ __launch_bounds__(256) void f_scatter_kernel(
    const int* __restrict__ par,
    const float* __restrict__ Uf,    // [256, 256]
    const float* __restrict__ Ufb,   // [256]
    int childStart, int ncShift, int parStart, int nd, int M)
{
    __shared__ float As[16][68];
    __shared__ float Bs[16][68];
    __shared__ int nodeb[64];
    __shared__ int slotb[64];

    int m0 = blockIdx.x * 64, n0 = blockIdx.y * 64;
    int tid = threadIdx.x;
    int tx = tid & 15, ty = tid >> 4;
    int lm = tid >> 2, lk = (tid & 3) * 4;

    if (tid < 64) {
        int r = m0 + tid;
        int node = -1, slot = 0;
        if (r < M) {
            int g = r >> ncShift;
            int i = r & ((1 << ncShift) - 1);
            node = g * NPG + childStart + i;
            int p = par[node];
            int g2 = p / NPG;
            slot = g2 * nd + (p - g2 * NPG - parStart);
        }
        nodeb[tid] = node;
        slotb[tid] = slot;
    }
    __syncthreads();

    float acc[4][4] = {};
    int mynode = nodeb[lm];
    const float* arow = (mynode >= 0) ? (g_h + (size_t)mynode * HDIM + lk) : nullptr;
    const float* brow = Uf + (size_t)(n0 + lm) * HDIM + lk;

    for (int k0 = 0; k0 < HDIM; k0 += 16) {
        float4 av = arow ? *(const float4*)(arow + k0) : make_float4(0.f, 0.f, 0.f, 0.f);
        As[lk + 0][lm] = av.x; As[lk + 1][lm] = av.y; As[lk + 2][lm] = av.z; As[lk + 3][lm] = av.w;
        float4 bv = *(const float4*)(brow + k0);
        Bs[lk + 0][lm] = bv.x; Bs[lk + 1][lm] = bv.y; Bs[lk + 2][lm] = bv.z; Bs[lk + 3][lm] = bv.w;
        __syncthreads();
#pragma unroll
        for (int kk = 0; kk < 16; ++kk) {
            float4 a4 = *(const float4*)&As[kk][ty * 4];
            float4 b4 = *(const float4*)&Bs[kk][tx * 4];
            float ar[4] = {a4.x, a4.y, a4.z, a4.w};
            float br[4] = {b4.x, b4.y, b4.z, b4.w};
#pragma unroll
            for (int i = 0; i < 4; ++i)
#pragma unroll
                for (int j = 0; j < 4; ++j) acc[i][j] += ar[i] * br[j];
        }
        __syncthreads();
    }

    float bb[4];
#pragma unroll
    for (int j = 0; j < 4; ++j) bb[j] = Ufb[n0 + tx * 4 + j];

#pragma unroll
    for (int i = 0; i < 4; ++i) {
        int rr = m0 + ty * 4 + i;
        if (rr >= M) continue;
        int node = nodeb[ty * 4 + i];
        int slot = slotb[ty * 4 + i];
        const float* hrow = g_h + (size_t)node * HDIM;
        const float* crow = g_c + (size_t)node * HDIM;
        float* caggrow = g_cagg + (size_t)slot * HDIM;
        float* htrow = g_htild + (size_t)slot * HDIM;
#pragma unroll
        for (int j = 0; j < 4; ++j) {
            int col = n0 + tx * 4 + j;
            float f = sigf(acc[i][j] + bb[j]);
            atomicAdd(caggrow + col, f * crow[col]);
            atomicAdd(htrow + col, hrow[col]);
        }
    }
}

// ============================================================================
// Kernel 3: g_uadd[r] = g_htild[r] @ U_iou^T for parents at level d (M rows).
// ============================================================================
__global__ __launch_bounds__(256) void uiou_kernel(
    const float* __restrict__ U,   // [768, 256]
    int M)
{
    __shared__ float As[16][68];
    __shared__ float Bs[16][68];
    int m0 = blockIdx.x * 64, n0 = blockIdx.y * 64;
    int tid = threadIdx.x;
    int tx = tid & 15, ty = tid >> 4;
    int lm = tid >> 2, lk = (tid & 3) * 4;

    float acc[4][4] = {};
    bool aval = (m0 + lm) < M;
    const float* arow = g_htild + (size_t)(m0 + lm) * HDIM + lk;
    const float* brow = U + (size_t)(n0 + lm) * HDIM + lk;

    for (int k0 = 0; k0 < HDIM; k0 += 16) {
        float4 av = aval ? *(const float4*)(arow + k0) : make_float4(0.f, 0.f, 0.f, 0.f);
        As[lk + 0][lm] = av.x; As[lk + 1][lm] = av.y; As[lk + 2][lm] = av.z; As[lk + 3][lm] = av.w;
        float4 bv = *(const float4*)(brow + k0);
        Bs[lk + 0][lm] = bv.x; Bs[lk + 1][lm] = bv.y; Bs[lk + 2][lm] = bv.z; Bs[lk + 3][lm] = bv.w;
        __syncthreads();
#pragma unroll
        for (int kk = 0; kk < 16; ++kk) {
            float4 a4 = *(const float4*)&As[kk][ty * 4];
            float4 b4 = *(const float4*)&Bs[kk][tx * 4];
            float ar[4] = {a4.x, a4.y, a4.z, a4.w};
            float br[4] = {b4.x, b4.y, b4.z, b4.w};
#pragma unroll
            for (int i = 0; i < 4; ++i)
#pragma unroll
                for (int j = 0; j < 4; ++j) acc[i][j] += ar[i] * br[j];
        }
        __syncthreads();
    }
#pragma unroll
    for (int i = 0; i < 4; ++i) {
        int rr = m0 + ty * 4 + i;
        if (rr < M) {
            float* o = g_uadd + (size_t)rr * IOUD + n0 + tx * 4;
#pragma unroll
            for (int j = 0; j < 4; ++j) o[j] = acc[i][j];
        }
    }
}

// ============================================================================
// Kernel 4: gates for level d.  One block per node row (M blocks, 256 threads).
// iou row = g_tab[x[node]] (+ g_uadd[r] if non-leaf); c = sig(i)*tanh(u)+cagg;
// h = sig(o)*tanh(c).
// ============================================================================
__global__ __launch_bounds__(256) void gates_kernel(
    const int* __restrict__ x, int nodeStart, int ndShift, int hasChild)
{
    int r = blockIdx.x;
    int j = threadIdx.x;
    int g = r >> ndShift;
    int node = g * NPG + nodeStart + (r & ((1 << ndShift) - 1));
    int xv = __ldg(x + node);
    const float* trow = g_tab + (size_t)xv * IOUD;
    float iv = trow[j];
    float ov = trow[256 + j];
    float uv = trow[512 + j];
    float cn;
    if (hasChild) {
        const float* ua = g_uadd + (size_t)r * IOUD;
        iv += ua[j]; ov += ua[256 + j]; uv += ua[512 + j];
        cn = sigf(iv) * tanhf(uv) + g_cagg[(size_t)r * HDIM + j];
    } else {
        cn = sigf(iv) * tanhf(uv);
    }
    g_c[(size_t)node * HDIM + j] = cn;
    g_h[(size_t)node * HDIM + j] = sigf(ov) * tanhf(cn);
}

// ============================================================================
// Kernel 5: zero the segment accumulators for one level (n elements each).
// ============================================================================
__global__ void zero_hc(int n)
{
    int i = blockIdx.x * blockDim.x + threadIdx.x;
    if (i < n) { g_htild[i] = 0.f; g_cagg[i] = 0.f; }
}

// ============================================================================
// Kernel 6: classifier.  out[g][c] = dot(h[root_g], lin_w[c]) + lin_b[c].
// One block per tree; 8 warps, warp w handles classes w, w+8, ...
// ============================================================================
__global__ __launch_bounds__(256) void classify_kernel(
    const float* __restrict__ lin_w,  // [104, 256]
    const float* __restrict__ lin_b,  // [104]
    float* __restrict__ out)          // [32, 104]
{
    int g = blockIdx.x;
    const float* hr = g_h + (size_t)g * NPG * HDIM;   // root node = g*NPG
    int warp = threadIdx.x >> 5, lane = threadIdx.x & 31;
    for (int cc = warp; cc < CDIM; cc += 8) {
        const float* w = lin_w + (size_t)cc * HDIM;
        float s = 0.f;
#pragma unroll
        for (int k = lane; k < HDIM; k += 32) s += hr[k] * w[k];
#pragma unroll
        for (int off = 16; off; off >>= 1) s += __shfl_xor_sync(0xffffffffu, s, off);
        if (lane == 0) out[g * CDIM + cc] = s + lin_b[cc];
    }
}

// ============================================================================
// Host
// ============================================================================
extern "C" void kernel_launch(void* const* d_in, const int* in_sizes, int n_in,
                              void* d_out, int out_size)
{
    const int*   x      = (const int*)  d_in[0];
    const int*   par    = (const int*)  d_in[1];
    const float* emb    = (const float*)d_in[2];
    const float* W_iou  = (const float*)d_in[3];
    const float* U_iou  = (const float*)d_in[4];
    const float* b_iou  = (const float*)d_in[5];
    const float* U_f_w  = (const float*)d_in[6];
    const float* U_f_b  = (const float*)d_in[7];
    const float* lin_w  = (const float*)d_in[8];
    const float* lin_b  = (const float*)d_in[9];
    float* out = (float*)d_out;

    static const int STARTS_H[12] = {0, 1, 3, 7, 15, 31, 63, 127, 255, 511, 1023, 2047};

    // Phase 1: vocab table (emb @ W_iou^T + b_iou) — 20000 rows instead of 131040
    {
        dim3 grid((VOCABSZ + 63) / 64, IOUD / 64);
        tab_kernel<<<grid, 256>>>(emb, W_iou, b_iou);
    }

    // Phase 2: topological sweep, leaves (d=11) -> root (d=0)
    for (int d = 11; d >= 0; --d) {
        int nd = 1 << d;
        int M = NTREES * nd;            // parents at this level
        if (d < 11) {
            int Mc = NTREES * (nd << 1); // children at level d+1
            int zn = M * HDIM;
            zero_hc<<<(zn + 255) / 256, 256>>>(zn);
            dim3 gf((Mc + 63) / 64, HDIM / 64);
            f_scatter_kernel<<<gf, 256>>>(par, U_f_w, U_f_b,
                                          STARTS_H[d + 1], d + 1, STARTS_H[d], nd, Mc);
            dim3 gu((M + 63) / 64, IOUD / 64);
            uiou_kernel<<<gu, 256>>>(U_iou, M);
        }
        gates_kernel<<<M, 256>>>(x, STARTS_H[d], d, d < 11 ? 1 : 0);
    }

    // Phase 3: classifier on the 32 roots
    classify_kernel<<<NTREES, 256>>>(lin_w, lin_b, out);
}

// round 11
// speedup vs baseline: 1.6939x; 1.6939x over previous
#include <cuda_runtime.h>
#include <math.h>
#include <stdint.h>

// ---------------- problem constants ----------------
#define NTREES   32
#define NPG      4095
#define NTOT     (NTREES * NPG)      // 131040
#define HDIM     256
#define IOUD     768
#define CDIM     104
#define VOCABSZ  20000
#define PADTOK   (VOCABSZ - 1)

// ---------------- scratch (device globals) ----------------
__device__ float g_tab  [(size_t)VOCABSZ * IOUD];            // emb @ W_iou^T + b_iou
__device__ float g_h    [(size_t)NTOT * HDIM];
__device__ float g_c    [(size_t)NTOT * HDIM];
__device__ float g_htild[2][(size_t)NTREES * 1024 * HDIM];   // parity double-buffer
__device__ float g_cagg [2][(size_t)NTREES * 1024 * HDIM];
__device__ float g_uadd [(size_t)NTREES * 1024 * IOUD];

__device__ __forceinline__ float sigf(float v) { return 1.f / (1.f + __expf(-v)); }

__device__ __forceinline__ uint32_t f2tf32(float x) {
    uint32_t u; asm("cvt.rna.tf32.f32 %0, %1;" : "=r"(u) : "f"(x)); return u;
}
__device__ __forceinline__ void mma_tf32(float* d, const uint32_t* a, const uint32_t* b) {
    asm volatile(
        "mma.sync.aligned.m16n8k8.row.col.f32.tf32.tf32.f32 "
        "{%0,%1,%2,%3},{%4,%5,%6,%7},{%8,%9},{%0,%1,%2,%3};"
        : "+f"(d[0]), "+f"(d[1]), "+f"(d[2]), "+f"(d[3])
        : "r"(a[0]), "r"(a[1]), "r"(a[2]), "r"(a[3]), "r"(b[0]), "r"(b[1]));
}
__device__ __forceinline__ void red2(float* addr, float x, float y) {
    asm volatile("red.global.add.v2.f32 [%0], {%1,%2};" :: "l"(addr), "f"(x), "f"(y) : "memory");
}

// ============================================================================
// Unified tf32 tensor-core GEMM: C[M,N] = A[M,256] @ B[N,256]^T (+bias)(+epilogue)
// MODE 0: tab    — A=emb (PAD row zeroed), C=g_tab, +b_iou
// MODE 1: f/scat — A=g_h rows via child-node map; f=sigmoid(acc+Ufb);
//                  red.v2: g_cagg[parity][slot] += f*c_child, g_htild[parity][slot] += h_child
// MODE 2: uiou   — A=g_htild[parity] rows, C=g_uadd, no bias
// Tile: BM=128, BN=128, BK=32. 256 threads = 8 warps (2m x 4n), warp tile 64x32.
// ============================================================================
template<int MODE>
__global__ __launch_bounds__(256) void mma_gemm(
    const float* __restrict__ Ag,     // MODE0: emb
    const float* __restrict__ Bg,     // [N,256] row-major weight
    const float* __restrict__ bias,   // MODE0: b_iou, MODE1: U_f_b
    const int*   __restrict__ par,
    int childStart, int ncShift, int parStart, int ndPar,
    int M, int parity)
{
    __shared__ uint32_t As[128][36];
    __shared__ uint32_t Bs[128][36];
    __shared__ int nodeb[128];
    __shared__ int slotb[128];

    const int tid  = threadIdx.x;
    const int m0   = blockIdx.x * 128;
    const int n0   = blockIdx.y * 128;
    const int lane = tid & 31;
    const int warp = tid >> 5;
    const int wm   = (warp & 1) * 64;
    const int wn   = (warp >> 1) * 32;

    if (MODE == 1) {
        if (tid < 128) {
            int r = m0 + tid, node = -1, slot = 0;
            if (r < M) {
                int g = r >> ncShift;
                int i = r - (g << ncShift);
                node = g * NPG + childStart + i;
                int p = par[node];
                int g2 = p / NPG;
                slot = g2 * ndPar + (p - g2 * NPG - parStart);
            }
            nodeb[tid] = node; slotb[tid] = slot;
        }
        __syncthreads();
    }

    // staging assignment: thread t loads row t>>1, k-half (t&1)*16 (4 float4 each)
    const int mRow = tid >> 1;
    const int kHalf = (tid & 1) * 16;
    const float* aPtr;
    bool aValid;
    if (MODE == 0) {
        int r = m0 + mRow;
        aValid = (r < M) && (r != PADTOK);
        aPtr = Ag + (size_t)(aValid ? r : 0) * 256 + kHalf;
    } else if (MODE == 1) {
        int node = nodeb[mRow];
        aValid = node >= 0;
        aPtr = g_h + (size_t)(aValid ? node : 0) * 256 + kHalf;
    } else {
        int r = m0 + mRow;
        aValid = r < M;
        aPtr = g_htild[parity] + (size_t)(aValid ? r : 0) * 256 + kHalf;
    }
    const float* bPtr = Bg + (size_t)(n0 + mRow) * 256 + kHalf;

    float acc[4][4][4];
#pragma unroll
    for (int i = 0; i < 4; ++i)
#pragma unroll
        for (int j = 0; j < 4; ++j)
#pragma unroll
            for (int e = 0; e < 4; ++e) acc[i][j][e] = 0.f;

    float4 ra[4], rb[4];
    const float4 z4 = make_float4(0.f, 0.f, 0.f, 0.f);
#pragma unroll
    for (int q = 0; q < 4; ++q) {
        ra[q] = aValid ? *(const float4*)(aPtr + q * 4) : z4;
        rb[q] = *(const float4*)(bPtr + q * 4);
    }

    for (int k0 = 0; k0 < 256; k0 += 32) {
        // store staged regs -> smem (with tf32 rounding)
#pragma unroll
        for (int q = 0; q < 4; ++q) {
            int c = kHalf + q * 4;
            As[mRow][c + 0] = f2tf32(ra[q].x); As[mRow][c + 1] = f2tf32(ra[q].y);
            As[mRow][c + 2] = f2tf32(ra[q].z); As[mRow][c + 3] = f2tf32(ra[q].w);
            Bs[mRow][c + 0] = f2tf32(rb[q].x); Bs[mRow][c + 1] = f2tf32(rb[q].y);
            Bs[mRow][c + 2] = f2tf32(rb[q].z); Bs[mRow][c + 3] = f2tf32(rb[q].w);
        }
        __syncthreads();
        if (k0 < 224) {
#pragma unroll
            for (int q = 0; q < 4; ++q) {
                ra[q] = aValid ? *(const float4*)(aPtr + k0 + 32 + q * 4) : z4;
                rb[q] = *(const float4*)(bPtr + k0 + 32 + q * 4);
            }
        }
#pragma unroll
        for (int kk = 0; kk < 4; ++kk) {
            const int krow = kk * 8 + (lane & 3);
            uint32_t a[4][4], b[4][2];
#pragma unroll
            for (int mi = 0; mi < 4; ++mi) {
                int r = wm + mi * 16 + (lane >> 2);
                a[mi][0] = As[r][krow];     a[mi][1] = As[r + 8][krow];
                a[mi][2] = As[r][krow + 4]; a[mi][3] = As[r + 8][krow + 4];
            }
#pragma unroll
            for (int nb = 0; nb < 4; ++nb) {
                int cn = wn + nb * 8 + (lane >> 2);
                b[nb][0] = Bs[cn][krow]; b[nb][1] = Bs[cn][krow + 4];
            }
#pragma unroll
            for (int mi = 0; mi < 4; ++mi)
#pragma unroll
                for (int nb = 0; nb < 4; ++nb)
                    mma_tf32(acc[mi][nb], a[mi], b[nb]);
        }
        __syncthreads();
    }

    // ---------------- epilogue ----------------
    const int cb = n0 + wn + (lane & 3) * 2;   // column of acc[..][nb][0] is cb + nb*8

    if (MODE == 1) {
        float2 bb[4];
#pragma unroll
        for (int nb = 0; nb < 4; ++nb) bb[nb] = *(const float2*)(bias + cb + nb * 8);
        float* caggB = g_cagg[parity];
        float* htB   = g_htild[parity];
#pragma unroll
        for (int mi = 0; mi < 4; ++mi) {
#pragma unroll
            for (int half = 0; half < 2; ++half) {
                int lr = wm + mi * 16 + (lane >> 2) + half * 8;
                int node = nodeb[lr];
                if (node < 0) continue;
                int slot = slotb[lr];
                const float* crow = g_c + (size_t)node * 256;
                const float* hrow = g_h + (size_t)node * 256;
                float* cdst = caggB + (size_t)slot * 256;
                float* hdst = htB   + (size_t)slot * 256;
#pragma unroll
                for (int nb = 0; nb < 4; ++nb) {
                    int c = cb + nb * 8;
                    float f0 = sigf(acc[mi][nb][half * 2 + 0] + bb[nb].x);
                    float f1 = sigf(acc[mi][nb][half * 2 + 1] + bb[nb].y);
                    float2 cv = *(const float2*)(crow + c);
                    red2(cdst + c, f0 * cv.x, f1 * cv.y);
                    float2 hv = *(const float2*)(hrow + c);
                    red2(hdst + c, hv.x, hv.y);
                }
            }
        }
    } else {
        float2 bb[4];
#pragma unroll
        for (int nb = 0; nb < 4; ++nb)
            bb[nb] = (MODE == 0) ? *(const float2*)(bias + cb + nb * 8)
                                 : make_float2(0.f, 0.f);
        float* Cout = (MODE == 0) ? g_tab : g_uadd;
#pragma unroll
        for (int mi = 0; mi < 4; ++mi) {
#pragma unroll
            for (int half = 0; half < 2; ++half) {
                int r = m0 + wm + mi * 16 + (lane >> 2) + half * 8;
                if (r >= M) continue;
                float* orow = Cout + (size_t)r * IOUD;
#pragma unroll
                for (int nb = 0; nb < 4; ++nb) {
                    int c = cb + nb * 8;
                    float2 v = make_float2(acc[mi][nb][half * 2 + 0] + bb[nb].x,
                                           acc[mi][nb][half * 2 + 1] + bb[nb].y);
                    *(float2*)(orow + c) = v;
                }
            }
        }
    }
}

// ============================================================================
// Gates: one block (64 threads, float4 lanes) per level-row.  Also zeroes the
// NEXT level's parity buffers (rows < zeroRows of parity zp).
// ============================================================================
__global__ __launch_bounds__(64) void gates_kernel(
    const int* __restrict__ x, int nodeStart, int ndShift, int hasChild,
    int cp, int zp, int zeroRows)
{
    int r  = blockIdx.x;
    int j4 = threadIdx.x;               // float4 index 0..63
    int g  = r >> ndShift;
    int node = g * NPG + nodeStart + (r - (g << ndShift));
    int xv = __ldg(x + node);
    const float4* trow = (const float4*)(g_tab + (size_t)xv * IOUD);
    float4 iv = trow[j4], ov = trow[64 + j4], uv = trow[128 + j4];
    float4 cn;
    if (hasChild) {
        const float4* ua = (const float4*)(g_uadd + (size_t)r * IOUD);
        float4 u0 = ua[j4], u1 = ua[64 + j4], u2 = ua[128 + j4];
        iv.x += u0.x; iv.y += u0.y; iv.z += u0.z; iv.w += u0.w;
        ov.x += u1.x; ov.y += u1.y; ov.z += u1.z; ov.w += u1.w;
        uv.x += u2.x; uv.y += u2.y; uv.z += u2.z; uv.w += u2.w;
        float4 ca = ((const float4*)(g_cagg[cp] + (size_t)r * HDIM))[j4];
        cn.x = sigf(iv.x) * tanhf(uv.x) + ca.x;
        cn.y = sigf(iv.y) * tanhf(uv.y) + ca.y;
        cn.z = sigf(iv.z) * tanhf(uv.z) + ca.z;
        cn.w = sigf(iv.w) * tanhf(uv.w) + ca.w;
    } else {
        cn.x = sigf(iv.x) * tanhf(uv.x);
        cn.y = sigf(iv.y) * tanhf(uv.y);
        cn.z = sigf(iv.z) * tanhf(uv.z);
        cn.w = sigf(iv.w) * tanhf(uv.w);
    }
    ((float4*)(g_c + (size_t)node * HDIM))[j4] = cn;
    float4 hn;
    hn.x = sigf(ov.x) * tanhf(cn.x);
    hn.y = sigf(ov.y) * tanhf(cn.y);
    hn.z = sigf(ov.z) * tanhf(cn.z);
    hn.w = sigf(ov.w) * tanhf(cn.w);
    ((float4*)(g_h + (size_t)node * HDIM))[j4] = hn;

    if (r < zeroRows) {
        float4 z = make_float4(0.f, 0.f, 0.f, 0.f);
        ((float4*)(g_htild[zp] + (size_t)r * HDIM))[j4] = z;
        ((float4*)(g_cagg[zp]  + (size_t)r * HDIM))[j4] = z;
    }
}

// ============================================================================
// Classifier: out[g][c] = dot(h[root_g], lin_w[c]) + lin_b[c]
// ============================================================================
__global__ __launch_bounds__(256) void classify_kernel(
    const float* __restrict__ lin_w, const float* __restrict__ lin_b,
    float* __restrict__ out)
{
    int g = blockIdx.x;
    const float* hr = g_h + (size_t)g * NPG * HDIM;
    int warp = threadIdx.x >> 5, lane = threadIdx.x & 31;
    for (int cc = warp; cc < CDIM; cc += 8) {
        const float* w = lin_w + (size_t)cc * HDIM;
        float s = 0.f;
#pragma unroll
        for (int k = lane; k < HDIM; k += 32) s += hr[k] * w[k];
#pragma unroll
        for (int off = 16; off; off >>= 1) s += __shfl_xor_sync(0xffffffffu, s, off);
        if (lane == 0) out[g * CDIM + cc] = s + lin_b[cc];
    }
}

// ============================================================================
// Host
// ============================================================================
extern "C" void kernel_launch(void* const* d_in, const int* in_sizes, int n_in,
                              void* d_out, int out_size)
{
    const int*   x      = (const int*)  d_in[0];
    const int*   par    = (const int*)  d_in[1];
    const float* emb    = (const float*)d_in[2];
    const float* W_iou  = (const float*)d_in[3];
    const float* U_iou  = (const float*)d_in[4];
    const float* b_iou  = (const float*)d_in[5];
    const float* U_f_w  = (const float*)d_in[6];
    const float* U_f_b  = (const float*)d_in[7];
    const float* lin_w  = (const float*)d_in[8];
    const float* lin_b  = (const float*)d_in[9];
    float* out = (float*)d_out;

    static const int STARTS_H[12] = {0, 1, 3, 7, 15, 31, 63, 127, 255, 511, 1023, 2047};

    // Phase 1: vocab table  g_tab = emb @ W_iou^T + b_iou
    mma_gemm<0><<<dim3((VOCABSZ + 127) / 128, IOUD / 128), 256>>>(
        emb, W_iou, b_iou, nullptr, 0, 0, 0, 0, VOCABSZ, 0);

    // Leaf level d=11 (no children); zero parity-0 buffers for level 10
    gates_kernel<<<NTREES << 11, 64>>>(x, STARTS_H[11], 11, 0,
                                       0, 0, NTREES << 10);

    // Phase 2: levels d=10..0
    for (int d = 10; d >= 0; --d) {
        int M  = NTREES << d;            // parents at level d
        int Mc = NTREES << (d + 1);      // children at level d+1
        int p  = d & 1;

        // forget-gate GEMM over children + segment reduction into parity-p buffers
        mma_gemm<1><<<dim3((Mc + 127) / 128, HDIM / 128), 256>>>(
            nullptr, U_f_w, U_f_b, par,
            STARTS_H[d + 1], d + 1, STARTS_H[d], 1 << d, Mc, p);

        // g_uadd = g_htild[p] @ U_iou^T
        mma_gemm<2><<<dim3((M + 127) / 128, IOUD / 128), 256>>>(
            nullptr, U_iou, nullptr, nullptr, 0, 0, 0, 0, M, p);

        // gates at level d; zero parity buffers for level d-1
        int zp = (d >= 1) ? ((d - 1) & 1) : 0;
        int zr = (d >= 1) ? (NTREES << (d - 1)) : 0;
        gates_kernel<<<M, 64>>>(x, STARTS_H[d], d, 1, p, zp, zr);
    }

    // Phase 3: classifier
    classify_kernel<<<NTREES, 256>>>(lin_w, lin_b, out);
}

// round 12
// speedup vs baseline: 1.6966x; 1.0015x over previous
#include <cuda_runtime.h>
#include <math.h>
#include <stdint.h>

// ---------------- problem constants ----------------
#define NTREES   32
#define NPG      4095
#define NTOT     (NTREES * NPG)      // 131040
#define HDIM     256
#define IOUD     768
#define CDIM     104
#define VOCABSZ  20000
#define PADTOK   (VOCABSZ - 1)

// ---------------- scratch (device globals) ----------------
__device__ float g_tab  [(size_t)VOCABSZ * IOUD];            // emb @ W_iou^T + b_iou
__device__ float g_h    [(size_t)NTOT * HDIM];
__device__ float g_c    [(size_t)NTOT * HDIM];
__device__ float g_htild[2][(size_t)NTREES * 1024 * HDIM];   // parity double-buffer
__device__ float g_cagg [2][(size_t)NTREES * 1024 * HDIM];
__device__ float g_uadd [(size_t)NTREES * 1024 * IOUD];

__device__ __forceinline__ float sigf(float v) { return 1.f / (1.f + __expf(-v)); }

__device__ __forceinline__ uint32_t f2tf32(float x) {
    uint32_t u; asm("cvt.rna.tf32.f32 %0, %1;" : "=r"(u) : "f"(x)); return u;
}
__device__ __forceinline__ void mma_tf32(float* d, const uint32_t* a, const uint32_t* b) {
    asm volatile(
        "mma.sync.aligned.m16n8k8.row.col.f32.tf32.tf32.f32 "
        "{%0,%1,%2,%3},{%4,%5,%6,%7},{%8,%9},{%0,%1,%2,%3};"
        : "+f"(d[0]), "+f"(d[1]), "+f"(d[2]), "+f"(d[3])
        : "r"(a[0]), "r"(a[1]), "r"(a[2]), "r"(a[3]), "r"(b[0]), "r"(b[1]));
}
__device__ __forceinline__ void red2(float* addr, float x, float y) {
    asm volatile("red.global.add.v2.f32 [%0], {%1,%2};" :: "l"(addr), "f"(x), "f"(y) : "memory");
}

// ============================================================================
// Unified tf32 tensor-core GEMM: C[M,N] = A[M,256] @ B[N,256]^T (+bias)(+epilogue)
// MODE 0: tab    — A=emb (PAD row zeroed), C=g_tab, +b_iou
// MODE 1: f/scat — A=g_h rows via child-node map; f=sigmoid(acc+Ufb);
//                  red.v2: g_cagg[parity][slot] += f*c_child, g_htild[parity][slot] += h_child
// MODE 2: uiou   — A=g_htild[parity] rows, C=g_uadd, no bias
// Tile: BM=128, BN=128, BK=32. 256 threads = 8 warps (2m x 4n), warp tile 64x32.
// ============================================================================
template<int MODE>
__global__ __launch_bounds__(256) void mma_gemm(
    const float* __restrict__ Ag,     // MODE0: emb
    const float* __restrict__ Bg,     // [N,256] row-major weight
    const float* __restrict__ bias,   // MODE0: b_iou, MODE1: U_f_b
    const int*   __restrict__ par,
    int childStart, int ncShift, int parStart, int ndPar,
    int M, int parity)
{
    __shared__ uint32_t As[128][36];
    __shared__ uint32_t Bs[128][36];
    __shared__ int nodeb[128];
    __shared__ int slotb[128];

    const int tid  = threadIdx.x;
    const int m0   = blockIdx.x * 128;
    const int n0   = blockIdx.y * 128;
    const int lane = tid & 31;
    const int warp = tid >> 5;
    const int wm   = (warp & 1) * 64;
    const int wn   = (warp >> 1) * 32;

    if (MODE == 1) {
        if (tid < 128) {
            int r = m0 + tid, node = -1, slot = 0;
            if (r < M) {
                int g = r >> ncShift;
                int i = r - (g << ncShift);
                node = g * NPG + childStart + i;
                int p = par[node];
                int g2 = p / NPG;
                slot = g2 * ndPar + (p - g2 * NPG - parStart);
            }
            nodeb[tid] = node; slotb[tid] = slot;
        }
        __syncthreads();
    }

    // staging assignment: thread t loads row t>>1, k-half (t&1)*16 (4 float4 each)
    const int mRow = tid >> 1;
    const int kHalf = (tid & 1) * 16;
    const float* aPtr;
    bool aValid;
    if (MODE == 0) {
        int r = m0 + mRow;
        aValid = (r < M) && (r != PADTOK);
        aPtr = Ag + (size_t)(aValid ? r : 0) * 256 + kHalf;
    } else if (MODE == 1) {
        int node = nodeb[mRow];
        aValid = node >= 0;
        aPtr = g_h + (size_t)(aValid ? node : 0) * 256 + kHalf;
    } else {
        int r = m0 + mRow;
        aValid = r < M;
        aPtr = g_htild[parity] + (size_t)(aValid ? r : 0) * 256 + kHalf;
    }
    const float* bPtr = Bg + (size_t)(n0 + mRow) * 256 + kHalf;

    float acc[4][4][4];
#pragma unroll
    for (int i = 0; i < 4; ++i)
#pragma unroll
        for (int j = 0; j < 4; ++j)
#pragma unroll
            for (int e = 0; e < 4; ++e) acc[i][j][e] = 0.f;

    float4 ra[4], rb[4];
    const float4 z4 = make_float4(0.f, 0.f, 0.f, 0.f);
#pragma unroll
    for (int q = 0; q < 4; ++q) {
        ra[q] = aValid ? *(const float4*)(aPtr + q * 4) : z4;
        rb[q] = *(const float4*)(bPtr + q * 4);
    }

    for (int k0 = 0; k0 < 256; k0 += 32) {
        // store staged regs -> smem (with tf32 rounding)
#pragma unroll
        for (int q = 0; q < 4; ++q) {
            int c = kHalf + q * 4;
            As[mRow][c + 0] = f2tf32(ra[q].x); As[mRow][c + 1] = f2tf32(ra[q].y);
            As[mRow][c + 2] = f2tf32(ra[q].z); As[mRow][c + 3] = f2tf32(ra[q].w);
            Bs[mRow][c + 0] = f2tf32(rb[q].x); Bs[mRow][c + 1] = f2tf32(rb[q].y);
            Bs[mRow][c + 2] = f2tf32(rb[q].z); Bs[mRow][c + 3] = f2tf32(rb[q].w);
        }
        __syncthreads();
        if (k0 < 224) {
#pragma unroll
            for (int q = 0; q < 4; ++q) {
                ra[q] = aValid ? *(const float4*)(aPtr + k0 + 32 + q * 4) : z4;
                rb[q] = *(const float4*)(bPtr + k0 + 32 + q * 4);
            }
        }
#pragma unroll
        for (int kk = 0; kk < 4; ++kk) {
            const int krow = kk * 8 + (lane & 3);
            uint32_t a[4][4], b[4][2];
#pragma unroll
            for (int mi = 0; mi < 4; ++mi) {
                int r = wm + mi * 16 + (lane >> 2);
                a[mi][0] = As[r][krow];     a[mi][1] = As[r + 8][krow];
                a[mi][2] = As[r][krow + 4]; a[mi][3] = As[r + 8][krow + 4];
            }
#pragma unroll
            for (int nb = 0; nb < 4; ++nb) {
                int cn = wn + nb * 8 + (lane >> 2);
                b[nb][0] = Bs[cn][krow]; b[nb][1] = Bs[cn][krow + 4];
            }
#pragma unroll
            for (int mi = 0; mi < 4; ++mi)
#pragma unroll
                for (int nb = 0; nb < 4; ++nb)
                    mma_tf32(acc[mi][nb], a[mi], b[nb]);
        }
        __syncthreads();
    }

    // ---------------- epilogue ----------------
    const int cb = n0 + wn + (lane & 3) * 2;   // column of acc[..][nb][0] is cb + nb*8

    if (MODE == 1) {
        float2 bb[4];
#pragma unroll
        for (int nb = 0; nb < 4; ++nb) bb[nb] = *(const float2*)(bias + cb + nb * 8);
        float* caggB = g_cagg[parity];
        float* htB   = g_htild[parity];
#pragma unroll
        for (int mi = 0; mi < 4; ++mi) {
#pragma unroll
            for (int half = 0; half < 2; ++half) {
                int lr = wm + mi * 16 + (lane >> 2) + half * 8;
                int node = nodeb[lr];
                if (node < 0) continue;
                int slot = slotb[lr];
                const float* crow = g_c + (size_t)node * 256;
                const float* hrow = g_h + (size_t)node * 256;
                float* cdst = caggB + (size_t)slot * 256;
                float* hdst = htB   + (size_t)slot * 256;
#pragma unroll
                for (int nb = 0; nb < 4; ++nb) {
                    int c = cb + nb * 8;
                    float f0 = sigf(acc[mi][nb][half * 2 + 0] + bb[nb].x);
                    float f1 = sigf(acc[mi][nb][half * 2 + 1] + bb[nb].y);
                    float2 cv = *(const float2*)(crow + c);
                    red2(cdst + c, f0 * cv.x, f1 * cv.y);
                    float2 hv = *(const float2*)(hrow + c);
                    red2(hdst + c, hv.x, hv.y);
                }
            }
        }
    } else {
        float2 bb[4];
#pragma unroll
        for (int nb = 0; nb < 4; ++nb)
            bb[nb] = (MODE == 0) ? *(const float2*)(bias + cb + nb * 8)
                                 : make_float2(0.f, 0.f);
        float* Cout = (MODE == 0) ? g_tab : g_uadd;
#pragma unroll
        for (int mi = 0; mi < 4; ++mi) {
#pragma unroll
            for (int half = 0; half < 2; ++half) {
                int r = m0 + wm + mi * 16 + (lane >> 2) + half * 8;
                if (r >= M) continue;
                float* orow = Cout + (size_t)r * IOUD;
#pragma unroll
                for (int nb = 0; nb < 4; ++nb) {
                    int c = cb + nb * 8;
                    float2 v = make_float2(acc[mi][nb][half * 2 + 0] + bb[nb].x,
                                           acc[mi][nb][half * 2 + 1] + bb[nb].y);
                    *(float2*)(orow + c) = v;
                }
            }
        }
    }
}

// ============================================================================
// Gates: one block (64 threads, float4 lanes) per level-row.  Also zeroes the
// NEXT level's parity buffers (rows < zeroRows of parity zp).
// ============================================================================
__global__ __launch_bounds__(64) void gates_kernel(
    const int* __restrict__ x, int nodeStart, int ndShift, int hasChild,
    int cp, int zp, int zeroRows)
{
    int r  = blockIdx.x;
    int j4 = threadIdx.x;               // float4 index 0..63
    int g  = r >> ndShift;
    int node = g * NPG + nodeStart + (r - (g << ndShift));
    int xv = __ldg(x + node);
    const float4* trow = (const float4*)(g_tab + (size_t)xv * IOUD);
    float4 iv = trow[j4], ov = trow[64 + j4], uv = trow[128 + j4];
    float4 cn;
    if (hasChild) {
        const float4* ua = (const float4*)(g_uadd + (size_t)r * IOUD);
        float4 u0 = ua[j4], u1 = ua[64 + j4], u2 = ua[128 + j4];
        iv.x += u0.x; iv.y += u0.y; iv.z += u0.z; iv.w += u0.w;
        ov.x += u1.x; ov.y += u1.y; ov.z += u1.z; ov.w += u1.w;
        uv.x += u2.x; uv.y += u2.y; uv.z += u2.z; uv.w += u2.w;
        float4 ca = ((const float4*)(g_cagg[cp] + (size_t)r * HDIM))[j4];
        cn.x = sigf(iv.x) * tanhf(uv.x) + ca.x;
        cn.y = sigf(iv.y) * tanhf(uv.y) + ca.y;
        cn.z = sigf(iv.z) * tanhf(uv.z) + ca.z;
        cn.w = sigf(iv.w) * tanhf(uv.w) + ca.w;
    } else {
        cn.x = sigf(iv.x) * tanhf(uv.x);
        cn.y = sigf(iv.y) * tanhf(uv.y);
        cn.z = sigf(iv.z) * tanhf(uv.z);
        cn.w = sigf(iv.w) * tanhf(uv.w);
    }
    ((float4*)(g_c + (size_t)node * HDIM))[j4] = cn;
    float4 hn;
    hn.x = sigf(ov.x) * tanhf(cn.x);
    hn.y = sigf(ov.y) * tanhf(cn.y);
    hn.z = sigf(ov.z) * tanhf(cn.z);
    hn.w = sigf(ov.w) * tanhf(cn.w);
    ((float4*)(g_h + (size_t)node * HDIM))[j4] = hn;

    if (r < zeroRows) {
        float4 z = make_float4(0.f, 0.f, 0.f, 0.f);
        ((float4*)(g_htild[zp] + (size_t)r * HDIM))[j4] = z;
        ((float4*)(g_cagg[zp]  + (size_t)r * HDIM))[j4] = z;
    }
}

// ============================================================================
// Classifier: out[g][c] = dot(h[root_g], lin_w[c]) + lin_b[c]
// ============================================================================
__global__ __launch_bounds__(256) void classify_kernel(
    const float* __restrict__ lin_w, const float* __restrict__ lin_b,
    float* __restrict__ out)
{
    int g = blockIdx.x;
    const float* hr = g_h + (size_t)g * NPG * HDIM;
    int warp = threadIdx.x >> 5, lane = threadIdx.x & 31;
    for (int cc = warp; cc < CDIM; cc += 8) {
        const float* w = lin_w + (size_t)cc * HDIM;
        float s = 0.f;
#pragma unroll
        for (int k = lane; k < HDIM; k += 32) s += hr[k] * w[k];
#pragma unroll
        for (int off = 16; off; off >>= 1) s += __shfl_xor_sync(0xffffffffu, s, off);
        if (lane == 0) out[g * CDIM + cc] = s + lin_b[cc];
    }
}

// ============================================================================
// Host
// ============================================================================
extern "C" void kernel_launch(void* const* d_in, const int* in_sizes, int n_in,
                              void* d_out, int out_size)
{
    const int*   x      = (const int*)  d_in[0];
    const int*   par    = (const int*)  d_in[1];
    const float* emb    = (const float*)d_in[2];
    const float* W_iou  = (const float*)d_in[3];
    const float* U_iou  = (const float*)d_in[4];
    const float* b_iou  = (const float*)d_in[5];
    const float* U_f_w  = (const float*)d_in[6];
    const float* U_f_b  = (const float*)d_in[7];
    const float* lin_w  = (const float*)d_in[8];
    const float* lin_b  = (const float*)d_in[9];
    float* out = (float*)d_out;

    static const int STARTS_H[12] = {0, 1, 3, 7, 15, 31, 63, 127, 255, 511, 1023, 2047};

    // Phase 1: vocab table  g_tab = emb @ W_iou^T + b_iou
    mma_gemm<0><<<dim3((VOCABSZ + 127) / 128, IOUD / 128), 256>>>(
        emb, W_iou, b_iou, nullptr, 0, 0, 0, 0, VOCABSZ, 0);

    // Leaf level d=11 (no children); zero parity-0 buffers for level 10
    gates_kernel<<<NTREES << 11, 64>>>(x, STARTS_H[11], 11, 0,
                                       0, 0, NTREES << 10);

    // Phase 2: levels d=10..0
    for (int d = 10; d >= 0; --d) {
        int M  = NTREES << d;            // parents at level d
        int Mc = NTREES << (d + 1);      // children at level d+1
        int p  = d & 1;

        // forget-gate GEMM over children + segment reduction into parity-p buffers
        mma_gemm<1><<<dim3((Mc + 127) / 128, HDIM / 128), 256>>>(
            nullptr, U_f_w, U_f_b, par,
            STARTS_H[d + 1], d + 1, STARTS_H[d], 1 << d, Mc, p);

        // g_uadd = g_htild[p] @ U_iou^T
        mma_gemm<2><<<dim3((M + 127) / 128, IOUD / 128), 256>>>(
            nullptr, U_iou, nullptr, nullptr, 0, 0, 0, 0, M, p);

        // gates at level d; zero parity buffers for level d-1
        int zp = (d >= 1) ? ((d - 1) & 1) : 0;
        int zr = (d >= 1) ? (NTREES << (d - 1)) : 0;
        gates_kernel<<<M, 64>>>(x, STARTS_H[d], d, 1, p, zp, zr);
    }

    // Phase 3: classifier
    classify_kernel<<<NTREES, 256>>>(lin_w, lin_b, out);
}

// round 13
// speedup vs baseline: 1.6969x; 1.0002x over previous
#include <cuda_runtime.h>
#include <math.h>
#include <stdint.h>

// ---------------- problem constants ----------------
#define NTREES   32
#define NPG      4095
#define NTOT     (NTREES * NPG)      // 131040
#define HDIM     256
#define IOUD     768
#define CDIM     104
#define VOCABSZ  20000
#define PADTOK   (VOCABSZ - 1)

// ---------------- scratch (device globals) ----------------
__device__ float g_tab  [(size_t)VOCABSZ * IOUD];            // emb @ W_iou^T + b_iou
__device__ float g_h    [(size_t)NTOT * HDIM];
__device__ float g_c    [(size_t)NTOT * HDIM];
__device__ float g_htild[2][(size_t)NTREES * 1024 * HDIM];   // parity double-buffer
__device__ float g_cagg [2][(size_t)NTREES * 1024 * HDIM];
__device__ float g_uadd [(size_t)NTREES * 1024 * IOUD];

__device__ __forceinline__ float sigf(float v) { return 1.f / (1.f + __expf(-v)); }

__device__ __forceinline__ uint32_t f2tf32(float x) {
    uint32_t u; asm("cvt.rna.tf32.f32 %0, %1;" : "=r"(u) : "f"(x)); return u;
}
__device__ __forceinline__ void mma_tf32(float* d, const uint32_t* a, const uint32_t* b) {
    asm volatile(
        "mma.sync.aligned.m16n8k8.row.col.f32.tf32.tf32.f32 "
        "{%0,%1,%2,%3},{%4,%5,%6,%7},{%8,%9},{%0,%1,%2,%3};"
        : "+f"(d[0]), "+f"(d[1]), "+f"(d[2]), "+f"(d[3])
        : "r"(a[0]), "r"(a[1]), "r"(a[2]), "r"(a[3]), "r"(b[0]), "r"(b[1]));
}
__device__ __forceinline__ void red2(float* addr, float x, float y) {
    asm volatile("red.global.add.v2.f32 [%0], {%1,%2};" :: "l"(addr), "f"(x), "f"(y) : "memory");
}

// ============================================================================
// Unified tf32 tensor-core GEMM: C[M,N] = A[M,256] @ B[N,256]^T (+bias)(+epilogue)
// MODE 0: tab    — A=emb (PAD row zeroed), C=g_tab, +b_iou
// MODE 1: f/scat — A=g_h rows via child-node map; f=sigmoid(acc+Ufb);
//                  red.v2: g_cagg[parity][slot] += f*c_child, g_htild[parity][slot] += h_child
// MODE 2: uiou   — A=g_htild[parity] rows, C=g_uadd, no bias
// Tile: BM=128, BN=128, BK=32. 256 threads = 8 warps (2m x 4n), warp tile 64x32.
// ============================================================================
template<int MODE>
__global__ __launch_bounds__(256) void mma_gemm(
    const float* __restrict__ Ag,     // MODE0: emb
    const float* __restrict__ Bg,     // [N,256] row-major weight
    const float* __restrict__ bias,   // MODE0: b_iou, MODE1: U_f_b
    const int*   __restrict__ par,
    int childStart, int ncShift, int parStart, int ndPar,
    int M, int parity)
{
    __shared__ uint32_t As[128][36];
    __shared__ uint32_t Bs[128][36];
    __shared__ int nodeb[128];
    __shared__ int slotb[128];

    const int tid  = threadIdx.x;
    const int m0   = blockIdx.x * 128;
    const int n0   = blockIdx.y * 128;
    const int lane = tid & 31;
    const int warp = tid >> 5;
    const int wm   = (warp & 1) * 64;
    const int wn   = (warp >> 1) * 32;

    if (MODE == 1) {
        if (tid < 128) {
            int r = m0 + tid, node = -1, slot = 0;
            if (r < M) {
                int g = r >> ncShift;
                int i = r - (g << ncShift);
                node = g * NPG + childStart + i;
                int p = par[node];
                int g2 = p / NPG;
                slot = g2 * ndPar + (p - g2 * NPG - parStart);
            }
            nodeb[tid] = node; slotb[tid] = slot;
        }
        __syncthreads();
    }

    // staging assignment: thread t loads row t>>1, k-half (t&1)*16 (4 float4 each)
    const int mRow = tid >> 1;
    const int kHalf = (tid & 1) * 16;
    const float* aPtr;
    bool aValid;
    if (MODE == 0) {
        int r = m0 + mRow;
        aValid = (r < M) && (r != PADTOK);
        aPtr = Ag + (size_t)(aValid ? r : 0) * 256 + kHalf;
    } else if (MODE == 1) {
        int node = nodeb[mRow];
        aValid = node >= 0;
        aPtr = g_h + (size_t)(aValid ? node : 0) * 256 + kHalf;
    } else {
        int r = m0 + mRow;
        aValid = r < M;
        aPtr = g_htild[parity] + (size_t)(aValid ? r : 0) * 256 + kHalf;
    }
    const float* bPtr = Bg + (size_t)(n0 + mRow) * 256 + kHalf;

    float acc[4][4][4];
#pragma unroll
    for (int i = 0; i < 4; ++i)
#pragma unroll
        for (int j = 0; j < 4; ++j)
#pragma unroll
            for (int e = 0; e < 4; ++e) acc[i][j][e] = 0.f;

    float4 ra[4], rb[4];
    const float4 z4 = make_float4(0.f, 0.f, 0.f, 0.f);
#pragma unroll
    for (int q = 0; q < 4; ++q) {
        ra[q] = aValid ? *(const float4*)(aPtr + q * 4) : z4;
        rb[q] = *(const float4*)(bPtr + q * 4);
    }

    for (int k0 = 0; k0 < 256; k0 += 32) {
        // store staged regs -> smem (with tf32 rounding)
#pragma unroll
        for (int q = 0; q < 4; ++q) {
            int c = kHalf + q * 4;
            As[mRow][c + 0] = f2tf32(ra[q].x); As[mRow][c + 1] = f2tf32(ra[q].y);
            As[mRow][c + 2] = f2tf32(ra[q].z); As[mRow][c + 3] = f2tf32(ra[q].w);
            Bs[mRow][c + 0] = f2tf32(rb[q].x); Bs[mRow][c + 1] = f2tf32(rb[q].y);
            Bs[mRow][c + 2] = f2tf32(rb[q].z); Bs[mRow][c + 3] = f2tf32(rb[q].w);
        }
        __syncthreads();
        if (k0 < 224) {
#pragma unroll
            for (int q = 0; q < 4; ++q) {
                ra[q] = aValid ? *(const float4*)(aPtr + k0 + 32 + q * 4) : z4;
                rb[q] = *(const float4*)(bPtr + k0 + 32 + q * 4);
            }
        }
#pragma unroll
        for (int kk = 0; kk < 4; ++kk) {
            const int krow = kk * 8 + (lane & 3);
            uint32_t a[4][4], b[4][2];
#pragma unroll
            for (int mi = 0; mi < 4; ++mi) {
                int r = wm + mi * 16 + (lane >> 2);
                a[mi][0] = As[r][krow];     a[mi][1] = As[r + 8][krow];
                a[mi][2] = As[r][krow + 4]; a[mi][3] = As[r + 8][krow + 4];
            }
#pragma unroll
            for (int nb = 0; nb < 4; ++nb) {
                int cn = wn + nb * 8 + (lane >> 2);
                b[nb][0] = Bs[cn][krow]; b[nb][1] = Bs[cn][krow + 4];
            }
#pragma unroll
            for (int mi = 0; mi < 4; ++mi)
#pragma unroll
                for (int nb = 0; nb < 4; ++nb)
                    mma_tf32(acc[mi][nb], a[mi], b[nb]);
        }
        __syncthreads();
    }

    // ---------------- epilogue ----------------
    const int cb = n0 + wn + (lane & 3) * 2;   // column of acc[..][nb][0] is cb + nb*8

    if (MODE == 1) {
        float2 bb[4];
#pragma unroll
        for (int nb = 0; nb < 4; ++nb) bb[nb] = *(const float2*)(bias + cb + nb * 8);
        float* caggB = g_cagg[parity];
        float* htB   = g_htild[parity];
#pragma unroll
        for (int mi = 0; mi < 4; ++mi) {
#pragma unroll
            for (int half = 0; half < 2; ++half) {
                int lr = wm + mi * 16 + (lane >> 2) + half * 8;
                int node = nodeb[lr];
                if (node < 0) continue;
                int slot = slotb[lr];
                const float* crow = g_c + (size_t)node * 256;
                const float* hrow = g_h + (size_t)node * 256;
                float* cdst = caggB + (size_t)slot * 256;
                float* hdst = htB   + (size_t)slot * 256;
#pragma unroll
                for (int nb = 0; nb < 4; ++nb) {
                    int c = cb + nb * 8;
                    float f0 = sigf(acc[mi][nb][half * 2 + 0] + bb[nb].x);
                    float f1 = sigf(acc[mi][nb][half * 2 + 1] + bb[nb].y);
                    float2 cv = *(const float2*)(crow + c);
                    red2(cdst + c, f0 * cv.x, f1 * cv.y);
                    float2 hv = *(const float2*)(hrow + c);
                    red2(hdst + c, hv.x, hv.y);
                }
            }
        }
    } else {
        float2 bb[4];
#pragma unroll
        for (int nb = 0; nb < 4; ++nb)
            bb[nb] = (MODE == 0) ? *(const float2*)(bias + cb + nb * 8)
                                 : make_float2(0.f, 0.f);
        float* Cout = (MODE == 0) ? g_tab : g_uadd;
#pragma unroll
        for (int mi = 0; mi < 4; ++mi) {
#pragma unroll
            for (int half = 0; half < 2; ++half) {
                int r = m0 + wm + mi * 16 + (lane >> 2) + half * 8;
                if (r >= M) continue;
                float* orow = Cout + (size_t)r * IOUD;
#pragma unroll
                for (int nb = 0; nb < 4; ++nb) {
                    int c = cb + nb * 8;
                    float2 v = make_float2(acc[mi][nb][half * 2 + 0] + bb[nb].x,
                                           acc[mi][nb][half * 2 + 1] + bb[nb].y);
                    *(float2*)(orow + c) = v;
                }
            }
        }
    }
}

// ============================================================================
// Gates: one block (64 threads, float4 lanes) per level-row.  Also zeroes the
// NEXT level's parity buffers (rows < zeroRows of parity zp).
// ============================================================================
__global__ __launch_bounds__(64) void gates_kernel(
    const int* __restrict__ x, int nodeStart, int ndShift, int hasChild,
    int cp, int zp, int zeroRows)
{
    int r  = blockIdx.x;
    int j4 = threadIdx.x;               // float4 index 0..63
    int g  = r >> ndShift;
    int node = g * NPG + nodeStart + (r - (g << ndShift));
    int xv = __ldg(x + node);
    const float4* trow = (const float4*)(g_tab + (size_t)xv * IOUD);
    float4 iv = trow[j4], ov = trow[64 + j4], uv = trow[128 + j4];
    float4 cn;
    if (hasChild) {
        const float4* ua = (const float4*)(g_uadd + (size_t)r * IOUD);
        float4 u0 = ua[j4], u1 = ua[64 + j4], u2 = ua[128 + j4];
        iv.x += u0.x; iv.y += u0.y; iv.z += u0.z; iv.w += u0.w;
        ov.x += u1.x; ov.y += u1.y; ov.z += u1.z; ov.w += u1.w;
        uv.x += u2.x; uv.y += u2.y; uv.z += u2.z; uv.w += u2.w;
        float4 ca = ((const float4*)(g_cagg[cp] + (size_t)r * HDIM))[j4];
        cn.x = sigf(iv.x) * tanhf(uv.x) + ca.x;
        cn.y = sigf(iv.y) * tanhf(uv.y) + ca.y;
        cn.z = sigf(iv.z) * tanhf(uv.z) + ca.z;
        cn.w = sigf(iv.w) * tanhf(uv.w) + ca.w;
    } else {
        cn.x = sigf(iv.x) * tanhf(uv.x);
        cn.y = sigf(iv.y) * tanhf(uv.y);
        cn.z = sigf(iv.z) * tanhf(uv.z);
        cn.w = sigf(iv.w) * tanhf(uv.w);
    }
    ((float4*)(g_c + (size_t)node * HDIM))[j4] = cn;
    float4 hn;
    hn.x = sigf(ov.x) * tanhf(cn.x);
    hn.y = sigf(ov.y) * tanhf(cn.y);
    hn.z = sigf(ov.z) * tanhf(cn.z);
    hn.w = sigf(ov.w) * tanhf(cn.w);
    ((float4*)(g_h + (size_t)node * HDIM))[j4] = hn;

    if (r < zeroRows) {
        float4 z = make_float4(0.f, 0.f, 0.f, 0.f);
        ((float4*)(g_htild[zp] + (size_t)r * HDIM))[j4] = z;
        ((float4*)(g_cagg[zp]  + (size_t)r * HDIM))[j4] = z;
    }
}

// ============================================================================
// Classifier: out[g][c] = dot(h[root_g], lin_w[c]) + lin_b[c]
// ============================================================================
__global__ __launch_bounds__(256) void classify_kernel(
    const float* __restrict__ lin_w, const float* __restrict__ lin_b,
    float* __restrict__ out)
{
    int g = blockIdx.x;
    const float* hr = g_h + (size_t)g * NPG * HDIM;
    int warp = threadIdx.x >> 5, lane = threadIdx.x & 31;
    for (int cc = warp; cc < CDIM; cc += 8) {
        const float* w = lin_w + (size_t)cc * HDIM;
        float s = 0.f;
#pragma unroll
        for (int k = lane; k < HDIM; k += 32) s += hr[k] * w[k];
#pragma unroll
        for (int off = 16; off; off >>= 1) s += __shfl_xor_sync(0xffffffffu, s, off);
        if (lane == 0) out[g * CDIM + cc] = s + lin_b[cc];
    }
}

// ============================================================================
// Host
// ============================================================================
extern "C" void kernel_launch(void* const* d_in, const int* in_sizes, int n_in,
                              void* d_out, int out_size)
{
    const int*   x      = (const int*)  d_in[0];
    const int*   par    = (const int*)  d_in[1];
    const float* emb    = (const float*)d_in[2];
    const float* W_iou  = (const float*)d_in[3];
    const float* U_iou  = (const float*)d_in[4];
    const float* b_iou  = (const float*)d_in[5];
    const float* U_f_w  = (const float*)d_in[6];
    const float* U_f_b  = (const float*)d_in[7];
    const float* lin_w  = (const float*)d_in[8];
    const float* lin_b  = (const float*)d_in[9];
    float* out = (float*)d_out;

    static const int STARTS_H[12] = {0, 1, 3, 7, 15, 31, 63, 127, 255, 511, 1023, 2047};

    // Phase 1: vocab table  g_tab = emb @ W_iou^T + b_iou
    mma_gemm<0><<<dim3((VOCABSZ + 127) / 128, IOUD / 128), 256>>>(
        emb, W_iou, b_iou, nullptr, 0, 0, 0, 0, VOCABSZ, 0);

    // Leaf level d=11 (no children); zero parity-0 buffers for level 10
    gates_kernel<<<NTREES << 11, 64>>>(x, STARTS_H[11], 11, 0,
                                       0, 0, NTREES << 10);

    // Phase 2: levels d=10..0
    for (int d = 10; d >= 0; --d) {
        int M  = NTREES << d;            // parents at level d
        int Mc = NTREES << (d + 1);      // children at level d+1
        int p  = d & 1;

        // forget-gate GEMM over children + segment reduction into parity-p buffers
        mma_gemm<1><<<dim3((Mc + 127) / 128, HDIM / 128), 256>>>(
            nullptr, U_f_w, U_f_b, par,
            STARTS_H[d + 1], d + 1, STARTS_H[d], 1 << d, Mc, p);

        // g_uadd = g_htild[p] @ U_iou^T
        mma_gemm<2><<<dim3((M + 127) / 128, IOUD / 128), 256>>>(
            nullptr, U_iou, nullptr, nullptr, 0, 0, 0, 0, M, p);

        // gates at level d; zero parity buffers for level d-1
        int zp = (d >= 1) ? ((d - 1) & 1) : 0;
        int zr = (d >= 1) ? (NTREES << (d - 1)) : 0;
        gates_kernel<<<M, 64>>>(x, STARTS_H[d], d, 1, p, zp, zr);
    }

    // Phase 3: classifier
    classify_kernel<<<NTREES, 256>>>(lin_w, lin_b, out);
}